// round 1
// baseline (speedup 1.0000x reference)
#include <cuda_runtime.h>
#include <math_constants.h>

#define Bn 4
#define Tn 1024
#define Cn 1024
#define Hn 16
#define Dn 64

// Scratch (device globals: allowed; no cudaMalloc anywhere)
__device__ float g_q[Bn * Hn * Tn * Dn];
__device__ float g_k[Bn * Hn * Tn * Dn];
__device__ float g_v[Bn * Hn * Tn * Dn];
__device__ float g_att[Bn * Tn * Hn * Dn];

// ---------------------------------------------------------------------------
// Kernel 1: fused QKV projection.
// Treat x as [4096, 1024] row-major. For each (proj, head) -> GEMM with
// W[h] of shape [C=1024, D=64] row-major. Output into g_q/g_k/g_v laid out
// [(b*H + h)*T + t]*D + d (head-major, ready for attention).
// Block tile: 128 (rows) x 64 (cols=D), K-chunk 8. 256 threads, 8x4 per thread.
// ---------------------------------------------------------------------------
__global__ __launch_bounds__(256) void qkv_gemm(
    const float* __restrict__ x,
    const float* __restrict__ Wq,
    const float* __restrict__ Wk,
    const float* __restrict__ Wv)
{
    __shared__ float As[8][128];   // k-major A tile
    __shared__ float Bs[8][64];

    const int tid = threadIdx.x;
    const int tx = tid & 15;       // 16 col-groups of 4
    const int ty = tid >> 4;       // 16 row-groups of 8

    const int rowBase = blockIdx.x * 128;           // 0..4095
    const int py = blockIdx.y;                      // 0..47
    const int proj = py >> 4;
    const int h = py & 15;

    const float* W = (proj == 0 ? Wq : (proj == 1 ? Wk : Wv)) + (size_t)h * Cn * Dn;
    float* outp = (proj == 0 ? g_q : (proj == 1 ? g_k : g_v));
    const int b  = rowBase >> 10;     // T = 1024 rows per batch
    const int t0 = rowBase & (Tn - 1);
    outp += ((size_t)(b * Hn + h) * Tn + t0) * Dn;

    const float* A = x + (size_t)rowBase * Cn;

    const int arow = tid >> 1;          // 0..127
    const int aseg = (tid & 1) * 4;     // 0 or 4 (k segment)
    const int brow = tid >> 5;          // 0..7  (k row)
    const int bcol = (tid & 31) * 2;    // 0..62

    float acc[8][4];
#pragma unroll
    for (int i = 0; i < 8; i++)
#pragma unroll
        for (int j = 0; j < 4; j++) acc[i][j] = 0.f;

    for (int k0 = 0; k0 < Cn; k0 += 8) {
        float4 av = *(const float4*)&A[(size_t)arow * Cn + k0 + aseg];
        float2 bv = *(const float2*)&W[(size_t)(k0 + brow) * Dn + bcol];
        As[aseg + 0][arow] = av.x;
        As[aseg + 1][arow] = av.y;
        As[aseg + 2][arow] = av.z;
        As[aseg + 3][arow] = av.w;
        *(float2*)&Bs[brow][bcol] = bv;
        __syncthreads();

#pragma unroll
        for (int k = 0; k < 8; k++) {
            float a[8], bb[4];
            *(float4*)&a[0] = *(const float4*)&As[k][ty * 8];
            *(float4*)&a[4] = *(const float4*)&As[k][ty * 8 + 4];
            *(float4*)&bb[0] = *(const float4*)&Bs[k][tx * 4];
#pragma unroll
            for (int i = 0; i < 8; i++)
#pragma unroll
                for (int j = 0; j < 4; j++)
                    acc[i][j] += a[i] * bb[j];
        }
        __syncthreads();
    }

#pragma unroll
    for (int i = 0; i < 8; i++) {
        float4 v = make_float4(acc[i][0], acc[i][1], acc[i][2], acc[i][3]);
        *(float4*)&outp[(size_t)(ty * 8 + i) * Dn + tx * 4] = v;
    }
}

// ---------------------------------------------------------------------------
// Kernel 2: causal flash attention, one block per (query-tile, b*H+h).
// 64 queries x D=64 per block, loops over key tiles of 64 with online softmax.
// Smem: Qt/Kt stored k-major (transposed) so the S-GEMM inner loop is all
// conflict-free float4 LDS; St (probabilities) stored [s][r] padded.
// Thread map: 256 threads = (tx 0..15) x (ty 0..15); thread owns S[4x4] and
// O[4 rows x 4 dcols]. Row statistics reduced over the tx half-warp via shfl.
// ---------------------------------------------------------------------------
#define SMEM_ATTN_FLOATS (4096 + 4096 + 64 * 68 + 64 * 65)

__global__ __launch_bounds__(256) void attn_kernel()
{
    extern __shared__ float sm[];
    float* Qt = sm;                        // [64 k][64 r]
    float* Kt = sm + 4096;                 // [64 k][64 s]
    float* Vs = sm + 8192;                 // [64 s][68]   (d padded)
    float* St = sm + 8192 + 64 * 68;       // [64 s][65]   (r padded)

    const int tid = threadIdx.x;
    const int tx = tid & 15;
    const int ty = tid >> 4;
    const int qt = (int)gridDim.x - 1 - (int)blockIdx.x;  // big tiles start first
    const int bh = blockIdx.y;

    const int ls = tid & 63;            // row (query or key index in tile)
    const int dseg = (tid >> 6) * 16;   // d segment

    // Load Q tile transposed: Qt[d][r]
    const float* qbase = g_q + ((size_t)bh * Tn + (size_t)qt * 64) * Dn;
#pragma unroll
    for (int q = 0; q < 4; q++) {
        float4 v = *(const float4*)&qbase[(size_t)ls * Dn + dseg + q * 4];
        Qt[(dseg + q * 4 + 0) * 64 + ls] = v.x;
        Qt[(dseg + q * 4 + 1) * 64 + ls] = v.y;
        Qt[(dseg + q * 4 + 2) * 64 + ls] = v.z;
        Qt[(dseg + q * 4 + 3) * 64 + ls] = v.w;
    }

    float m_i[4], l_i[4], oacc[4][4];
#pragma unroll
    for (int i = 0; i < 4; i++) {
        m_i[i] = -CUDART_INF_F;
        l_i[i] = 0.f;
#pragma unroll
        for (int j = 0; j < 4; j++) oacc[i][j] = 0.f;
    }

    for (int st = 0; st <= qt; st++) {
        const float* kbase = g_k + ((size_t)bh * Tn + (size_t)st * 64) * Dn;
        const float* vbase = g_v + ((size_t)bh * Tn + (size_t)st * 64) * Dn;
#pragma unroll
        for (int q = 0; q < 4; q++) {
            float4 kv = *(const float4*)&kbase[(size_t)ls * Dn + dseg + q * 4];
            Kt[(dseg + q * 4 + 0) * 64 + ls] = kv.x;
            Kt[(dseg + q * 4 + 1) * 64 + ls] = kv.y;
            Kt[(dseg + q * 4 + 2) * 64 + ls] = kv.z;
            Kt[(dseg + q * 4 + 3) * 64 + ls] = kv.w;
            float4 vv = *(const float4*)&vbase[(size_t)ls * Dn + dseg + q * 4];
            *(float4*)&Vs[ls * 68 + dseg + q * 4] = vv;
        }
        __syncthreads();

        // S = Q K^T for this tile
        float sc[4][4];
#pragma unroll
        for (int i = 0; i < 4; i++)
#pragma unroll
            for (int j = 0; j < 4; j++) sc[i][j] = 0.f;

        for (int k = 0; k < 64; k++) {
            float4 qv = *(const float4*)&Qt[k * 64 + ty * 4];
            float4 kv = *(const float4*)&Kt[k * 64 + tx * 4];
            sc[0][0] += qv.x * kv.x; sc[0][1] += qv.x * kv.y; sc[0][2] += qv.x * kv.z; sc[0][3] += qv.x * kv.w;
            sc[1][0] += qv.y * kv.x; sc[1][1] += qv.y * kv.y; sc[1][2] += qv.y * kv.z; sc[1][3] += qv.y * kv.w;
            sc[2][0] += qv.z * kv.x; sc[2][1] += qv.z * kv.y; sc[2][2] += qv.z * kv.z; sc[2][3] += qv.z * kv.w;
            sc[3][0] += qv.w * kv.x; sc[3][1] += qv.w * kv.y; sc[3][2] += qv.w * kv.z; sc[3][3] += qv.w * kv.w;
        }

        const float scale = 0.125f;  // 1/sqrt(64)
        const bool diag = (st == qt);
#pragma unroll
        for (int i = 0; i < 4; i++) {
            const int r = ty * 4 + i;
#pragma unroll
            for (int j = 0; j < 4; j++) {
                float s = sc[i][j] * scale;
                if (diag && (tx * 4 + j) > r) s = -CUDART_INF_F;
                sc[i][j] = s;
            }
            float tm = fmaxf(fmaxf(sc[i][0], sc[i][1]), fmaxf(sc[i][2], sc[i][3]));
            tm = fmaxf(tm, __shfl_xor_sync(0xffffffffu, tm, 1));
            tm = fmaxf(tm, __shfl_xor_sync(0xffffffffu, tm, 2));
            tm = fmaxf(tm, __shfl_xor_sync(0xffffffffu, tm, 4));
            tm = fmaxf(tm, __shfl_xor_sync(0xffffffffu, tm, 8));

            float nm = fmaxf(m_i[i], tm);
            float alpha = __expf(fmaxf(m_i[i] - nm, -80.f));
            float rs = 0.f;
#pragma unroll
            for (int j = 0; j < 4; j++) {
                float p = __expf(fmaxf(sc[i][j] - nm, -80.f));
                sc[i][j] = p;
                rs += p;
            }
            rs += __shfl_xor_sync(0xffffffffu, rs, 1);
            rs += __shfl_xor_sync(0xffffffffu, rs, 2);
            rs += __shfl_xor_sync(0xffffffffu, rs, 4);
            rs += __shfl_xor_sync(0xffffffffu, rs, 8);

            l_i[i] = l_i[i] * alpha + rs;
            m_i[i] = nm;
#pragma unroll
            for (int j = 0; j < 4; j++) oacc[i][j] *= alpha;
#pragma unroll
            for (int j = 0; j < 4; j++) St[(tx * 4 + j) * 65 + r] = sc[i][j];
        }
        __syncthreads();

        // O += P * V
        for (int s = 0; s < 64; s++) {
            float4 vv = *(const float4*)&Vs[s * 68 + tx * 4];
            float p0 = St[s * 65 + ty * 4 + 0];
            float p1 = St[s * 65 + ty * 4 + 1];
            float p2 = St[s * 65 + ty * 4 + 2];
            float p3 = St[s * 65 + ty * 4 + 3];
            oacc[0][0] += p0 * vv.x; oacc[0][1] += p0 * vv.y; oacc[0][2] += p0 * vv.z; oacc[0][3] += p0 * vv.w;
            oacc[1][0] += p1 * vv.x; oacc[1][1] += p1 * vv.y; oacc[1][2] += p1 * vv.z; oacc[1][3] += p1 * vv.w;
            oacc[2][0] += p2 * vv.x; oacc[2][1] += p2 * vv.y; oacc[2][2] += p2 * vv.z; oacc[2][3] += p2 * vv.w;
            oacc[3][0] += p3 * vv.x; oacc[3][1] += p3 * vv.y; oacc[3][2] += p3 * vv.z; oacc[3][3] += p3 * vv.w;
        }
        __syncthreads();
    }

    // Write O into g_att with [b][t][h*D + d] layout for the final projection
    const int b = bh >> 4, h = bh & 15;
    float* ob = g_att + ((size_t)b * Tn + (size_t)qt * 64) * (Hn * Dn) + h * Dn;
#pragma unroll
    for (int i = 0; i < 4; i++) {
        float inv = 1.f / l_i[i];
        float4 v = make_float4(oacc[i][0] * inv, oacc[i][1] * inv,
                               oacc[i][2] * inv, oacc[i][3] * inv);
        *(float4*)&ob[(size_t)(ty * 4 + i) * (Hn * Dn) + tx * 4] = v;
    }
}

// ---------------------------------------------------------------------------
// Kernel 3: output projection. g_att [4096, 1024] @ Wp [1024, 1024] + bp.
// Same tiling as qkv_gemm; block tile 128 x 64.
// ---------------------------------------------------------------------------
__global__ __launch_bounds__(256) void proj_gemm(
    const float* __restrict__ Wp,
    const float* __restrict__ bp,
    float* __restrict__ out)
{
    __shared__ float As[8][128];
    __shared__ float Bs[8][64];

    const int tid = threadIdx.x;
    const int tx = tid & 15;
    const int ty = tid >> 4;

    const int rowBase = blockIdx.x * 128;   // 0..4095
    const int n0 = blockIdx.y * 64;         // 0..960

    const float* A = g_att + (size_t)rowBase * (Hn * Dn);
    float* O = out + (size_t)rowBase * Cn + n0;

    const int arow = tid >> 1;
    const int aseg = (tid & 1) * 4;
    const int brow = tid >> 5;
    const int bcol = (tid & 31) * 2;

    float acc[8][4];
#pragma unroll
    for (int i = 0; i < 8; i++)
#pragma unroll
        for (int j = 0; j < 4; j++) acc[i][j] = 0.f;

    for (int k0 = 0; k0 < Hn * Dn; k0 += 8) {
        float4 av = *(const float4*)&A[(size_t)arow * (Hn * Dn) + k0 + aseg];
        float2 bv = *(const float2*)&Wp[(size_t)(k0 + brow) * Cn + n0 + bcol];
        As[aseg + 0][arow] = av.x;
        As[aseg + 1][arow] = av.y;
        As[aseg + 2][arow] = av.z;
        As[aseg + 3][arow] = av.w;
        *(float2*)&Bs[brow][bcol] = bv;
        __syncthreads();

#pragma unroll
        for (int k = 0; k < 8; k++) {
            float a[8], bb[4];
            *(float4*)&a[0] = *(const float4*)&As[k][ty * 8];
            *(float4*)&a[4] = *(const float4*)&As[k][ty * 8 + 4];
            *(float4*)&bb[0] = *(const float4*)&Bs[k][tx * 4];
#pragma unroll
            for (int i = 0; i < 8; i++)
#pragma unroll
                for (int j = 0; j < 4; j++)
                    acc[i][j] += a[i] * bb[j];
        }
        __syncthreads();
    }

#pragma unroll
    for (int i = 0; i < 8; i++) {
        float b0 = bp[n0 + tx * 4 + 0];
        float b1 = bp[n0 + tx * 4 + 1];
        float b2 = bp[n0 + tx * 4 + 2];
        float b3 = bp[n0 + tx * 4 + 3];
        float4 v = make_float4(acc[i][0] + b0, acc[i][1] + b1,
                               acc[i][2] + b2, acc[i][3] + b3);
        *(float4*)&O[(size_t)(ty * 8 + i) * Cn + tx * 4] = v;
    }
}

// ---------------------------------------------------------------------------

extern "C" void kernel_launch(void* const* d_in, const int* in_sizes, int n_in,
                              void* d_out, int out_size)
{
    (void)in_sizes; (void)n_in; (void)out_size;
    const float* x  = (const float*)d_in[0];
    const float* Wq = (const float*)d_in[1];
    const float* Wk = (const float*)d_in[2];
    const float* Wv = (const float*)d_in[3];
    const float* Wp = (const float*)d_in[4];
    const float* bp = (const float*)d_in[5];
    float* out = (float*)d_out;

    const size_t attn_smem = SMEM_ATTN_FLOATS * sizeof(float);  // ~65.3 KB
    cudaFuncSetAttribute(attn_kernel,
                         cudaFuncAttributeMaxDynamicSharedMemorySize,
                         (int)attn_smem);

    qkv_gemm<<<dim3(32, 48), 256>>>(x, Wq, Wk, Wv);
    attn_kernel<<<dim3(Tn / 64, Bn * Hn), 256, attn_smem>>>();
    proj_gemm<<<dim3(32, 16), 256>>>(Wp, bp, out);
}

// round 2
// speedup vs baseline: 1.7900x; 1.7900x over previous
#include <cuda_runtime.h>
#include <math_constants.h>
#include <cstdint>

#define Bn 4
#define Tn 1024
#define Cn 1024
#define Hn 16
#define Dn 64

// Scratch (device globals: allowed; no cudaMalloc anywhere)
__device__ float g_q[Bn * Hn * Tn * Dn];
__device__ float g_k[Bn * Hn * Tn * Dn];
__device__ float g_v[Bn * Hn * Tn * Dn];
__device__ float g_att[Bn * Tn * Hn * Dn];

// ---------------------------------------------------------------------------
// tf32 helpers
// ---------------------------------------------------------------------------
__device__ __forceinline__ uint32_t f2tf(float x) {
    uint32_t u;
    asm("cvt.rna.tf32.f32 %0, %1;" : "=r"(u) : "f"(x));
    return u;
}

__device__ __forceinline__ void mma_tf32(float c[4],
                                         uint32_t a0, uint32_t a1, uint32_t a2, uint32_t a3,
                                         uint32_t b0, uint32_t b1)
{
    asm volatile(
        "mma.sync.aligned.m16n8k8.row.col.f32.tf32.tf32.f32 "
        "{%0,%1,%2,%3}, {%4,%5,%6,%7}, {%8,%9}, {%0,%1,%2,%3};"
        : "+f"(c[0]), "+f"(c[1]), "+f"(c[2]), "+f"(c[3])
        : "r"(a0), "r"(a1), "r"(a2), "r"(a3), "r"(b0), "r"(b1));
}

// ---------------------------------------------------------------------------
// Kernel 1: fused QKV projection on tf32 tensor cores.
// x [4096,1024] row-major; per (proj,head) GEMM vs W[h] [1024,64] row-major.
// Block tile 128x64, K-chunk 32. 8 warps = (4 m) x (2 n), warp tile 32x32,
// fragments m16n8k8. Smem strides: A 36 floats, B 72 floats (both verified
// conflict-free for fragment LDS patterns).
// ---------------------------------------------------------------------------
__global__ __launch_bounds__(256, 2) void qkv_gemm_tc(
    const float* __restrict__ x,
    const float* __restrict__ Wq,
    const float* __restrict__ Wk,
    const float* __restrict__ Wv)
{
    __shared__ uint32_t As[128 * 36];
    __shared__ uint32_t Bs[32 * 72];

    const int tid = threadIdx.x;
    const int lane = tid & 31;
    const int warp = tid >> 5;
    const int wmBase = (warp & 3) * 32;
    const int wnBase = (warp >> 2) * 32;

    const int rowBase = blockIdx.x * 128;
    const int py = blockIdx.y;
    const int proj = py >> 4;
    const int h = py & 15;

    const float* W = (proj == 0 ? Wq : (proj == 1 ? Wk : Wv)) + (size_t)h * Cn * Dn;
    float* outp = (proj == 0 ? g_q : (proj == 1 ? g_k : g_v));
    const int b  = rowBase >> 10;
    const int t0 = rowBase & (Tn - 1);
    outp += ((size_t)(b * Hn + h) * Tn + t0) * Dn;

    const float* A = x + (size_t)rowBase * Cn;

    const int aRow = tid >> 3;        // 0..31
    const int aCol = (tid & 7) * 4;   // 0..28
    const int bRow = tid >> 3;        // 0..31

    float4 aR[4], bR[2];
    // prefetch stage 0
#pragma unroll
    for (int i = 0; i < 4; i++)
        aR[i] = *(const float4*)&A[(size_t)(aRow + i * 32) * Cn + aCol];
#pragma unroll
    for (int i = 0; i < 2; i++)
        bR[i] = *(const float4*)&W[(size_t)bRow * Dn + ((tid & 7) * 2 + i) * 4];

    float acc[2][4][4];
#pragma unroll
    for (int mt = 0; mt < 2; mt++)
#pragma unroll
        for (int j = 0; j < 4; j++)
#pragma unroll
            for (int e = 0; e < 4; e++) acc[mt][j][e] = 0.f;

    const int g  = lane >> 2;
    const int tg = lane & 3;

    for (int k0 = 0; k0 < Cn; k0 += 32) {
        // fill smem (with tf32 rounding)
#pragma unroll
        for (int i = 0; i < 4; i++) {
            int r = aRow + i * 32;
            As[r * 36 + aCol + 0] = f2tf(aR[i].x);
            As[r * 36 + aCol + 1] = f2tf(aR[i].y);
            As[r * 36 + aCol + 2] = f2tf(aR[i].z);
            As[r * 36 + aCol + 3] = f2tf(aR[i].w);
        }
#pragma unroll
        for (int i = 0; i < 2; i++) {
            int c = ((tid & 7) * 2 + i) * 4;
            Bs[bRow * 72 + c + 0] = f2tf(bR[i].x);
            Bs[bRow * 72 + c + 1] = f2tf(bR[i].y);
            Bs[bRow * 72 + c + 2] = f2tf(bR[i].z);
            Bs[bRow * 72 + c + 3] = f2tf(bR[i].w);
        }
        __syncthreads();

        if (k0 + 32 < Cn) {
#pragma unroll
            for (int i = 0; i < 4; i++)
                aR[i] = *(const float4*)&A[(size_t)(aRow + i * 32) * Cn + k0 + 32 + aCol];
#pragma unroll
            for (int i = 0; i < 2; i++)
                bR[i] = *(const float4*)&W[(size_t)(k0 + 32 + bRow) * Dn + ((tid & 7) * 2 + i) * 4];
        }

#pragma unroll
        for (int kk = 0; kk < 4; kk++) {
            const int kb = kk * 8;
            uint32_t af[2][4], bf[4][2];
#pragma unroll
            for (int mt = 0; mt < 2; mt++) {
                int r = wmBase + mt * 16 + g;
                af[mt][0] = As[r * 36 + kb + tg];
                af[mt][1] = As[(r + 8) * 36 + kb + tg];
                af[mt][2] = As[r * 36 + kb + tg + 4];
                af[mt][3] = As[(r + 8) * 36 + kb + tg + 4];
            }
#pragma unroll
            for (int j = 0; j < 4; j++) {
                int cidx = wnBase + j * 8 + g;
                bf[j][0] = Bs[(kb + tg) * 72 + cidx];
                bf[j][1] = Bs[(kb + tg + 4) * 72 + cidx];
            }
#pragma unroll
            for (int mt = 0; mt < 2; mt++)
#pragma unroll
                for (int j = 0; j < 4; j++)
                    mma_tf32(acc[mt][j], af[mt][0], af[mt][1], af[mt][2], af[mt][3],
                             bf[j][0], bf[j][1]);
        }
        __syncthreads();
    }

    // epilogue
#pragma unroll
    for (int mt = 0; mt < 2; mt++) {
        int row0 = wmBase + mt * 16 + g;
#pragma unroll
        for (int j = 0; j < 4; j++) {
            int col = wnBase + j * 8 + tg * 2;
            float2 lo = make_float2(acc[mt][j][0], acc[mt][j][1]);
            float2 hi = make_float2(acc[mt][j][2], acc[mt][j][3]);
            *(float2*)&outp[(size_t)row0 * Dn + col] = lo;
            *(float2*)&outp[(size_t)(row0 + 8) * Dn + col] = hi;
        }
    }
}

// ---------------------------------------------------------------------------
// Kernel 2: causal flash attention (unchanged from R1 — port to mma next).
// ---------------------------------------------------------------------------
#define SMEM_ATTN_FLOATS (4096 + 4096 + 64 * 68 + 64 * 65)

__global__ __launch_bounds__(256) void attn_kernel()
{
    extern __shared__ float sm[];
    float* Qt = sm;                        // [64 k][64 r]
    float* Kt = sm + 4096;                 // [64 k][64 s]
    float* Vs = sm + 8192;                 // [64 s][68]
    float* St = sm + 8192 + 64 * 68;       // [64 s][65]

    const int tid = threadIdx.x;
    const int tx = tid & 15;
    const int ty = tid >> 4;
    const int qt = (int)gridDim.x - 1 - (int)blockIdx.x;
    const int bh = blockIdx.y;

    const int ls = tid & 63;
    const int dseg = (tid >> 6) * 16;

    const float* qbase = g_q + ((size_t)bh * Tn + (size_t)qt * 64) * Dn;
#pragma unroll
    for (int q = 0; q < 4; q++) {
        float4 v = *(const float4*)&qbase[(size_t)ls * Dn + dseg + q * 4];
        Qt[(dseg + q * 4 + 0) * 64 + ls] = v.x;
        Qt[(dseg + q * 4 + 1) * 64 + ls] = v.y;
        Qt[(dseg + q * 4 + 2) * 64 + ls] = v.z;
        Qt[(dseg + q * 4 + 3) * 64 + ls] = v.w;
    }

    float m_i[4], l_i[4], oacc[4][4];
#pragma unroll
    for (int i = 0; i < 4; i++) {
        m_i[i] = -CUDART_INF_F;
        l_i[i] = 0.f;
#pragma unroll
        for (int j = 0; j < 4; j++) oacc[i][j] = 0.f;
    }

    for (int st = 0; st <= qt; st++) {
        const float* kbase = g_k + ((size_t)bh * Tn + (size_t)st * 64) * Dn;
        const float* vbase = g_v + ((size_t)bh * Tn + (size_t)st * 64) * Dn;
#pragma unroll
        for (int q = 0; q < 4; q++) {
            float4 kv = *(const float4*)&kbase[(size_t)ls * Dn + dseg + q * 4];
            Kt[(dseg + q * 4 + 0) * 64 + ls] = kv.x;
            Kt[(dseg + q * 4 + 1) * 64 + ls] = kv.y;
            Kt[(dseg + q * 4 + 2) * 64 + ls] = kv.z;
            Kt[(dseg + q * 4 + 3) * 64 + ls] = kv.w;
            float4 vv = *(const float4*)&vbase[(size_t)ls * Dn + dseg + q * 4];
            *(float4*)&Vs[ls * 68 + dseg + q * 4] = vv;
        }
        __syncthreads();

        float sc[4][4];
#pragma unroll
        for (int i = 0; i < 4; i++)
#pragma unroll
            for (int j = 0; j < 4; j++) sc[i][j] = 0.f;

        for (int k = 0; k < 64; k++) {
            float4 qv = *(const float4*)&Qt[k * 64 + ty * 4];
            float4 kv = *(const float4*)&Kt[k * 64 + tx * 4];
            sc[0][0] += qv.x * kv.x; sc[0][1] += qv.x * kv.y; sc[0][2] += qv.x * kv.z; sc[0][3] += qv.x * kv.w;
            sc[1][0] += qv.y * kv.x; sc[1][1] += qv.y * kv.y; sc[1][2] += qv.y * kv.z; sc[1][3] += qv.y * kv.w;
            sc[2][0] += qv.z * kv.x; sc[2][1] += qv.z * kv.y; sc[2][2] += qv.z * kv.z; sc[2][3] += qv.z * kv.w;
            sc[3][0] += qv.w * kv.x; sc[3][1] += qv.w * kv.y; sc[3][2] += qv.w * kv.z; sc[3][3] += qv.w * kv.w;
        }

        const float scale = 0.125f;
        const bool diag = (st == qt);
#pragma unroll
        for (int i = 0; i < 4; i++) {
            const int r = ty * 4 + i;
#pragma unroll
            for (int j = 0; j < 4; j++) {
                float s = sc[i][j] * scale;
                if (diag && (tx * 4 + j) > r) s = -CUDART_INF_F;
                sc[i][j] = s;
            }
            float tm = fmaxf(fmaxf(sc[i][0], sc[i][1]), fmaxf(sc[i][2], sc[i][3]));
            tm = fmaxf(tm, __shfl_xor_sync(0xffffffffu, tm, 1));
            tm = fmaxf(tm, __shfl_xor_sync(0xffffffffu, tm, 2));
            tm = fmaxf(tm, __shfl_xor_sync(0xffffffffu, tm, 4));
            tm = fmaxf(tm, __shfl_xor_sync(0xffffffffu, tm, 8));

            float nm = fmaxf(m_i[i], tm);
            float alpha = __expf(fmaxf(m_i[i] - nm, -80.f));
            float rs = 0.f;
#pragma unroll
            for (int j = 0; j < 4; j++) {
                float p = __expf(fmaxf(sc[i][j] - nm, -80.f));
                sc[i][j] = p;
                rs += p;
            }
            rs += __shfl_xor_sync(0xffffffffu, rs, 1);
            rs += __shfl_xor_sync(0xffffffffu, rs, 2);
            rs += __shfl_xor_sync(0xffffffffu, rs, 4);
            rs += __shfl_xor_sync(0xffffffffu, rs, 8);

            l_i[i] = l_i[i] * alpha + rs;
            m_i[i] = nm;
#pragma unroll
            for (int j = 0; j < 4; j++) oacc[i][j] *= alpha;
#pragma unroll
            for (int j = 0; j < 4; j++) St[(tx * 4 + j) * 65 + r] = sc[i][j];
        }
        __syncthreads();

        for (int s = 0; s < 64; s++) {
            float4 vv = *(const float4*)&Vs[s * 68 + tx * 4];
            float p0 = St[s * 65 + ty * 4 + 0];
            float p1 = St[s * 65 + ty * 4 + 1];
            float p2 = St[s * 65 + ty * 4 + 2];
            float p3 = St[s * 65 + ty * 4 + 3];
            oacc[0][0] += p0 * vv.x; oacc[0][1] += p0 * vv.y; oacc[0][2] += p0 * vv.z; oacc[0][3] += p0 * vv.w;
            oacc[1][0] += p1 * vv.x; oacc[1][1] += p1 * vv.y; oacc[1][2] += p1 * vv.z; oacc[1][3] += p1 * vv.w;
            oacc[2][0] += p2 * vv.x; oacc[2][1] += p2 * vv.y; oacc[2][2] += p2 * vv.z; oacc[2][3] += p2 * vv.w;
            oacc[3][0] += p3 * vv.x; oacc[3][1] += p3 * vv.y; oacc[3][2] += p3 * vv.z; oacc[3][3] += p3 * vv.w;
        }
        __syncthreads();
    }

    const int b = bh >> 4, h = bh & 15;
    float* ob = g_att + ((size_t)b * Tn + (size_t)qt * 64) * (Hn * Dn) + h * Dn;
#pragma unroll
    for (int i = 0; i < 4; i++) {
        float inv = 1.f / l_i[i];
        float4 v = make_float4(oacc[i][0] * inv, oacc[i][1] * inv,
                               oacc[i][2] * inv, oacc[i][3] * inv);
        *(float4*)&ob[(size_t)(ty * 4 + i) * (Hn * Dn) + tx * 4] = v;
    }
}

// ---------------------------------------------------------------------------
// Kernel 3: output projection on tf32 tensor cores.
// g_att [4096,1024] @ Wp [1024,1024] + bp. Same tiling as qkv_gemm_tc.
// ---------------------------------------------------------------------------
__global__ __launch_bounds__(256, 2) void proj_gemm_tc(
    const float* __restrict__ Wp,
    const float* __restrict__ bp,
    float* __restrict__ out)
{
    __shared__ uint32_t As[128 * 36];
    __shared__ uint32_t Bs[32 * 72];

    const int tid = threadIdx.x;
    const int lane = tid & 31;
    const int warp = tid >> 5;
    const int wmBase = (warp & 3) * 32;
    const int wnBase = (warp >> 2) * 32;

    const int rowBase = blockIdx.x * 128;
    const int n0 = blockIdx.y * 64;

    const float* A = g_att + (size_t)rowBase * Cn;
    float* O = out + (size_t)rowBase * Cn + n0;

    const int aRow = tid >> 3;
    const int aCol = (tid & 7) * 4;
    const int bRow = tid >> 3;

    float4 aR[4], bR[2];
#pragma unroll
    for (int i = 0; i < 4; i++)
        aR[i] = *(const float4*)&A[(size_t)(aRow + i * 32) * Cn + aCol];
#pragma unroll
    for (int i = 0; i < 2; i++)
        bR[i] = *(const float4*)&Wp[(size_t)bRow * Cn + n0 + ((tid & 7) * 2 + i) * 4];

    float acc[2][4][4];
#pragma unroll
    for (int mt = 0; mt < 2; mt++)
#pragma unroll
        for (int j = 0; j < 4; j++)
#pragma unroll
            for (int e = 0; e < 4; e++) acc[mt][j][e] = 0.f;

    const int g  = lane >> 2;
    const int tg = lane & 3;

    for (int k0 = 0; k0 < Cn; k0 += 32) {
#pragma unroll
        for (int i = 0; i < 4; i++) {
            int r = aRow + i * 32;
            As[r * 36 + aCol + 0] = f2tf(aR[i].x);
            As[r * 36 + aCol + 1] = f2tf(aR[i].y);
            As[r * 36 + aCol + 2] = f2tf(aR[i].z);
            As[r * 36 + aCol + 3] = f2tf(aR[i].w);
        }
#pragma unroll
        for (int i = 0; i < 2; i++) {
            int c = ((tid & 7) * 2 + i) * 4;
            Bs[bRow * 72 + c + 0] = f2tf(bR[i].x);
            Bs[bRow * 72 + c + 1] = f2tf(bR[i].y);
            Bs[bRow * 72 + c + 2] = f2tf(bR[i].z);
            Bs[bRow * 72 + c + 3] = f2tf(bR[i].w);
        }
        __syncthreads();

        if (k0 + 32 < Cn) {
#pragma unroll
            for (int i = 0; i < 4; i++)
                aR[i] = *(const float4*)&A[(size_t)(aRow + i * 32) * Cn + k0 + 32 + aCol];
#pragma unroll
            for (int i = 0; i < 2; i++)
                bR[i] = *(const float4*)&Wp[(size_t)(k0 + 32 + bRow) * Cn + n0 + ((tid & 7) * 2 + i) * 4];
        }

#pragma unroll
        for (int kk = 0; kk < 4; kk++) {
            const int kb = kk * 8;
            uint32_t af[2][4], bf[4][2];
#pragma unroll
            for (int mt = 0; mt < 2; mt++) {
                int r = wmBase + mt * 16 + g;
                af[mt][0] = As[r * 36 + kb + tg];
                af[mt][1] = As[(r + 8) * 36 + kb + tg];
                af[mt][2] = As[r * 36 + kb + tg + 4];
                af[mt][3] = As[(r + 8) * 36 + kb + tg + 4];
            }
#pragma unroll
            for (int j = 0; j < 4; j++) {
                int cidx = wnBase + j * 8 + g;
                bf[j][0] = Bs[(kb + tg) * 72 + cidx];
                bf[j][1] = Bs[(kb + tg + 4) * 72 + cidx];
            }
#pragma unroll
            for (int mt = 0; mt < 2; mt++)
#pragma unroll
                for (int j = 0; j < 4; j++)
                    mma_tf32(acc[mt][j], af[mt][0], af[mt][1], af[mt][2], af[mt][3],
                             bf[j][0], bf[j][1]);
        }
        __syncthreads();
    }

#pragma unroll
    for (int mt = 0; mt < 2; mt++) {
        int row0 = wmBase + mt * 16 + g;
#pragma unroll
        for (int j = 0; j < 4; j++) {
            int col = wnBase + j * 8 + tg * 2;
            float b0 = bp[n0 + col];
            float b1 = bp[n0 + col + 1];
            float2 lo = make_float2(acc[mt][j][0] + b0, acc[mt][j][1] + b1);
            float2 hi = make_float2(acc[mt][j][2] + b0, acc[mt][j][3] + b1);
            *(float2*)&O[(size_t)row0 * Cn + col] = lo;
            *(float2*)&O[(size_t)(row0 + 8) * Cn + col] = hi;
        }
    }
}

// ---------------------------------------------------------------------------

extern "C" void kernel_launch(void* const* d_in, const int* in_sizes, int n_in,
                              void* d_out, int out_size)
{
    (void)in_sizes; (void)n_in; (void)out_size;
    const float* x  = (const float*)d_in[0];
    const float* Wq = (const float*)d_in[1];
    const float* Wk = (const float*)d_in[2];
    const float* Wv = (const float*)d_in[3];
    const float* Wp = (const float*)d_in[4];
    const float* bp = (const float*)d_in[5];
    float* out = (float*)d_out;

    const size_t attn_smem = SMEM_ATTN_FLOATS * sizeof(float);
    cudaFuncSetAttribute(attn_kernel,
                         cudaFuncAttributeMaxDynamicSharedMemorySize,
                         (int)attn_smem);

    qkv_gemm_tc<<<dim3(32, 48), 256>>>(x, Wq, Wk, Wv);
    attn_kernel<<<dim3(Tn / 64, Bn * Hn), 256, attn_smem>>>();
    proj_gemm_tc<<<dim3(32, 16), 256>>>(Wp, bp, out);
}